// round 8
// baseline (speedup 1.0000x reference)
#include <cuda_runtime.h>
#include <cuda_fp16.h>
#include <cuda_bf16.h>

#define B_  8
#define Q_  256
#define K_  1024
#define D_  256
#define H_  128
#define DV_ 128

#define RPAD 132          // padded row stride in 4-byte words (33 float4)

// scratch: projected q (dup half2), k (paired half2), raw scores
// g_k2[b][kt][j][h] = (k[b][kt*128+j][h], k[b][kt*128+j+64][h])
__device__ __half2 g_q2[B_ * Q_ * H_];
__device__ __half2 g_k2[B_ * 8 * 64 * H_];
__device__ float   g_sc[B_ * Q_ * K_];

__device__ __forceinline__ __half2 tanh_h2(__half2 x) {
    __half2 y;
    asm("tanh.approx.f16x2 %0, %1;"
        : "=r"(*(unsigned int*)&y) : "r"(*(unsigned int*)&x));
    return y;
}

// ---------------------------------------------------------------------------
// Kernel 1a: K projection only. All blocks read the SAME W_k (128KB) -> W_k
// stays L1-resident per SM. 512 blocks, 256 threads, 16 rows/block,
// 8 rows per thread, scalar coalesced W loads + broadcast LDS.
// ---------------------------------------------------------------------------
__global__ __launch_bounds__(256) void proj_k_kernel(
    const float* __restrict__ keys, const float* __restrict__ Wk)
{
    __shared__ float s_in[16 * D_];   // 16KB
    int rb = blockIdx.x * 16;         // row within keys [0, 8192)

    int tid = threadIdx.x;
    int h  = tid & 127;
    int r0 = (tid >> 7) * 8;          // 0 or 8

    const float4* s4 = (const float4*)(keys + rb * D_);
    float4* d4 = (float4*)s_in;
    #pragma unroll
    for (int i = 0; i < 4; i++) d4[tid + 256 * i] = s4[tid + 256 * i];
    __syncthreads();

    float acc[8];
    #pragma unroll
    for (int r = 0; r < 8; r++) acc[r] = 0.f;

    #pragma unroll 4
    for (int d = 0; d < D_; d += 4) {
        float w0 = Wk[(d + 0) * H_ + h];
        float w1 = Wk[(d + 1) * H_ + h];
        float w2 = Wk[(d + 2) * H_ + h];
        float w3 = Wk[(d + 3) * H_ + h];
        #pragma unroll
        for (int r = 0; r < 8; r++) {
            float4 a = *(const float4*)&s_in[(r0 + r) * D_ + d];
            acc[r] += a.x * w0 + a.y * w1 + a.z * w2 + a.w * w3;
        }
    }

    int rk0 = rb + r0;
    #pragma unroll
    for (int r = 0; r < 8; r++) {
        int rk  = rk0 + r;
        int b   = rk >> 10;
        int rbi = rk & 1023;
        int kt  = rbi >> 7;
        int jj  = rbi & 127;
        int j    = jj & 63;
        int slot = jj >> 6;
        ((__half*)g_k2)[((((b * 8 + kt) * 64 + j) * H_) + h) * 2 + slot] =
            __float2half(acc[r]);
    }
}

// ---------------------------------------------------------------------------
// Kernel 1b: Q projection only. All blocks read the SAME W_q. 256 blocks,
// 256 threads, 8 rows/block, 4 rows per thread. Writes dup half2.
// ---------------------------------------------------------------------------
__global__ __launch_bounds__(256) void proj_q_kernel(
    const float* __restrict__ queries, const float* __restrict__ Wq)
{
    __shared__ float s_in[8 * D_];    // 8KB
    int rb = blockIdx.x * 8;          // row within queries [0, 2048)

    int tid = threadIdx.x;
    int h  = tid & 127;
    int r0 = (tid >> 7) * 4;          // 0 or 4

    const float4* s4 = (const float4*)(queries + rb * D_);
    float4* d4 = (float4*)s_in;
    #pragma unroll
    for (int i = 0; i < 2; i++) d4[tid + 256 * i] = s4[tid + 256 * i];
    __syncthreads();

    float acc[4];
    #pragma unroll
    for (int r = 0; r < 4; r++) acc[r] = 0.f;

    #pragma unroll 4
    for (int d = 0; d < D_; d += 4) {
        float w0 = Wq[(d + 0) * H_ + h];
        float w1 = Wq[(d + 1) * H_ + h];
        float w2 = Wq[(d + 2) * H_ + h];
        float w3 = Wq[(d + 3) * H_ + h];
        #pragma unroll
        for (int r = 0; r < 4; r++) {
            float4 a = *(const float4*)&s_in[(r0 + r) * D_ + d];
            acc[r] += a.x * w0 + a.y * w1 + a.z * w2 + a.w * w3;
        }
    }

    #pragma unroll
    for (int r = 0; r < 4; r++) {
        __half v = __float2half(acc[r]);
        g_q2[(rb + r0 + r) * H_ + h] = __halves2half2(v, v);
    }
}

// ---------------------------------------------------------------------------
// Kernel 2: scores only (UNCHANGED). grid (Q/8, K/128, B), 256 threads.
// ---------------------------------------------------------------------------
__global__ __launch_bounds__(256) void scores_kernel(const float* __restrict__ w_v)
{
    __shared__ float ksw[64 * RPAD];
    __shared__ float qsw[8 * RPAD];
    __shared__ float wvs[RPAD];

    int b  = blockIdx.z;
    int kt = blockIdx.y;
    int q0 = blockIdx.x * 8;
    int tid = threadIdx.x;

    const float4* srck = (const float4*)(g_k2 + (b * 8 + kt) * 64 * H_);
    #pragma unroll
    for (int l = 0; l < 8; l++) {
        int i = tid + 256 * l;
        int r = i >> 5, c = i & 31;
        *(float4*)(ksw + r * RPAD + c * 4) = srck[i];
    }
    {
        int r = tid >> 5, c = tid & 31;
        *(float4*)(qsw + r * RPAD + c * 4) =
            ((const float4*)(g_q2 + (b * Q_ + q0 + r) * H_))[c];
    }
    if (tid < 128) {
        __half v = __float2half(w_v[tid]);
        ((__half2*)wvs)[tid] = __halves2half2(v, v);
    }
    __syncthreads();

    int qg = tid >> 6;
    int j  = tid & 63;
    const float4* qa4 = (const float4*)(qsw + (qg * 2    ) * RPAD);
    const float4* qb4 = (const float4*)(qsw + (qg * 2 + 1) * RPAD);
    const float4* kp4 = (const float4*)(ksw + j * RPAD);
    const float4* wv4 = (const float4*)wvs;

    float S00 = 0.f, S01 = 0.f, S10 = 0.f, S11 = 0.f;
    #pragma unroll 4
    for (int hh = 0; hh < 16; hh++) {
        __half2 sa = __float2half2_rn(0.f);
        __half2 sb = __float2half2_rn(0.f);
        #pragma unroll
        for (int t = 0; t < 2; t++) {
            int h4 = hh * 2 + t;
            float4 kv = kp4[h4];
            float4 qa = qa4[h4];
            float4 qb = qb4[h4];
            float4 wf = wv4[h4];
            const __half2* kh  = (const __half2*)&kv;
            const __half2* qah = (const __half2*)&qa;
            const __half2* qbh = (const __half2*)&qb;
            const __half2* wh  = (const __half2*)&wf;
            #pragma unroll
            for (int u = 0; u < 4; u++) {
                __half2 ta = tanh_h2(__hadd2(qah[u], kh[u]));
                __half2 tb = tanh_h2(__hadd2(qbh[u], kh[u]));
                sa = __hfma2(wh[u], ta, sa);
                sb = __hfma2(wh[u], tb, sb);
            }
        }
        float2 fa = __half22float2(sa);
        float2 fb = __half22float2(sb);
        S00 += fa.x; S01 += fa.y;
        S10 += fb.x; S11 += fb.y;
    }

    float* dst = g_sc + (b * Q_ + q0 + qg * 2) * K_ + kt * 128;
    dst[j]           = S00;
    dst[j + 64]      = S01;
    dst[K_ + j]      = S10;
    dst[K_ + j + 64] = S11;
}

// ---------------------------------------------------------------------------
// Kernel 3: masked softmax + attn @ values (UNCHANGED). grid (Q/8, B).
// ---------------------------------------------------------------------------
__global__ __launch_bounds__(256) void smax_av_kernel(
    const float* __restrict__ values, const int* __restrict__ valid_lens,
    float* __restrict__ out)
{
    __shared__ float sc[8 * K_];

    int b  = blockIdx.y;
    int q0 = blockIdx.x * 8;
    int tid = threadIdx.x;
    int wid = tid >> 5, lane = tid & 31;
    int vlen = valid_lens[b];

    {
        const float* row = g_sc + (b * Q_ + q0 + wid) * K_;
        float v[32];
        float m = -3e38f;
        #pragma unroll
        for (int jj = 0; jj < 32; jj++) {
            int k = lane + 32 * jj;
            float s = (k < vlen) ? row[k] : -1e6f;
            v[jj] = s;
            m = fmaxf(m, s);
        }
        #pragma unroll
        for (int off = 16; off; off >>= 1)
            m = fmaxf(m, __shfl_xor_sync(0xffffffffu, m, off));
        float sum = 0.f;
        #pragma unroll
        for (int jj = 0; jj < 32; jj++) { v[jj] = __expf(v[jj] - m); sum += v[jj]; }
        #pragma unroll
        for (int off = 16; off; off >>= 1)
            sum += __shfl_xor_sync(0xffffffffu, sum, off);
        float inv = 1.f / sum;
        #pragma unroll
        for (int jj = 0; jj < 32; jj++)
            sc[wid * K_ + lane + 32 * jj] = v[jj] * inv;
    }
    __syncthreads();

    int v4 = tid & 31;
    int slice = tid >> 5;
    float4 acc[8];
    #pragma unroll
    for (int r = 0; r < 8; r++) acc[r] = make_float4(0.f, 0.f, 0.f, 0.f);
    const float4* vb = (const float4*)(values + b * K_ * DV_);
    #pragma unroll 4
    for (int k = slice; k < K_; k += 8) {
        float4 vv = vb[k * 32 + v4];
        #pragma unroll
        for (int r = 0; r < 8; r++) {
            float a = sc[r * K_ + k];
            acc[r].x += a * vv.x; acc[r].y += a * vv.y;
            acc[r].z += a * vv.z; acc[r].w += a * vv.w;
        }
    }
    __syncthreads();
    float4* red = (float4*)sc;
    #pragma unroll
    for (int r = 0; r < 8; r++) red[(slice * 8 + r) * 32 + v4] = acc[r];
    __syncthreads();
    {
        int r = tid >> 5, c = tid & 31;
        float4 o = make_float4(0.f, 0.f, 0.f, 0.f);
        #pragma unroll
        for (int s = 0; s < 8; s++) {
            float4 t = red[(s * 8 + r) * 32 + c];
            o.x += t.x; o.y += t.y; o.z += t.z; o.w += t.w;
        }
        ((float4*)(out + (b * Q_ + q0 + r) * DV_))[c] = o;
    }
}

extern "C" void kernel_launch(void* const* d_in, const int* in_sizes, int n_in,
                              void* d_out, int out_size)
{
    const float* queries    = (const float*)d_in[0];
    const float* keys       = (const float*)d_in[1];
    const float* values     = (const float*)d_in[2];
    const int*   valid_lens = (const int*)  d_in[3];
    const float* W_q        = (const float*)d_in[4];
    const float* W_k        = (const float*)d_in[5];
    const float* w_v        = (const float*)d_in[6];
    float* out = (float*)d_out;

    proj_k_kernel<<<(B_ * K_) / 16, 256>>>(keys, W_k);
    proj_q_kernel<<<(B_ * Q_) / 8, 256>>>(queries, W_q);
    scores_kernel<<<dim3(Q_ / 8, K_ / 128, B_), 256>>>(w_v);
    smax_av_kernel<<<dim3(Q_ / 8, B_), 256>>>(values, valid_lens, out);
}

// round 9
// speedup vs baseline: 1.5925x; 1.5925x over previous
#include <cuda_runtime.h>
#include <cuda_fp16.h>
#include <cuda_bf16.h>

#define B_  8
#define Q_  256
#define K_  1024
#define D_  256
#define H_  128
#define DV_ 128

#define RPAD 132          // padded row stride in 4-byte words (33 float4)

// scratch: projected q (dup half2), k (paired half2), raw scores
// g_k2[b][kt][j][h] = (k[b][kt*128+j][h], k[b][kt*128+j+64][h])
__device__ __half2 g_q2[B_ * Q_ * H_];
__device__ __half2 g_k2[B_ * 8 * 64 * H_];
__device__ float   g_sc[B_ * Q_ * K_];

__device__ __forceinline__ __half2 tanh_h2(__half2 x) {
    __half2 y;
    asm("tanh.approx.f16x2 %0, %1;"
        : "=r"(*(unsigned int*)&y) : "r"(*(unsigned int*)&x));
    return y;
}

// ---------------------------------------------------------------------------
// Kernel 1: fused projections (round-5 measured-best form).
// 256 threads, 16 rows/block; halves own 8 rows each. Scalar coalesced W
// loads + broadcast LDS of staged input rows.
// ---------------------------------------------------------------------------
__global__ __launch_bounds__(256) void proj_kernel(
    const float* __restrict__ queries, const float* __restrict__ keys,
    const float* __restrict__ Wq, const float* __restrict__ Wk)
{
    __shared__ float s_in[16 * D_];   // 16KB
    int rb = blockIdx.x * 16;
    bool isQ = rb < B_ * Q_;
    const float* src = isQ ? (queries + rb * D_) : (keys + (rb - B_ * Q_) * D_);
    const float* W   = isQ ? Wq : Wk;

    int tid = threadIdx.x;
    int h  = tid & 127;
    int r0 = (tid >> 7) * 8;          // 0 or 8

    const float4* s4 = (const float4*)src;
    float4* d4 = (float4*)s_in;
    #pragma unroll
    for (int i = 0; i < 4; i++) d4[tid + 256 * i] = s4[tid + 256 * i];
    __syncthreads();

    float acc[8];
    #pragma unroll
    for (int r = 0; r < 8; r++) acc[r] = 0.f;

    #pragma unroll 4
    for (int d = 0; d < D_; d += 4) {
        float w0 = W[(d + 0) * H_ + h];
        float w1 = W[(d + 1) * H_ + h];
        float w2 = W[(d + 2) * H_ + h];
        float w3 = W[(d + 3) * H_ + h];
        #pragma unroll
        for (int r = 0; r < 8; r++) {
            float4 a = *(const float4*)&s_in[(r0 + r) * D_ + d];
            acc[r] += a.x * w0 + a.y * w1 + a.z * w2 + a.w * w3;
        }
    }

    if (isQ) {
        #pragma unroll
        for (int r = 0; r < 8; r++) {
            __half v = __float2half(acc[r]);
            g_q2[(rb + r0 + r) * H_ + h] = __halves2half2(v, v);
        }
    } else {
        int rk0 = rb - B_ * Q_ + r0;
        #pragma unroll
        for (int r = 0; r < 8; r++) {
            int rk  = rk0 + r;
            int b   = rk >> 10;
            int rbi = rk & 1023;
            int kt  = rbi >> 7;
            int jj  = rbi & 127;
            int j    = jj & 63;
            int slot = jj >> 6;
            ((__half*)g_k2)[((((b * 8 + kt) * 64 + j) * H_) + h) * 2 + slot] =
                __float2half(acc[r]);
        }
    }
}

// ---------------------------------------------------------------------------
// Kernel 2: scores only (FROZEN). grid (Q/8, K/128, B), 256 threads.
// ---------------------------------------------------------------------------
__global__ __launch_bounds__(256) void scores_kernel(const float* __restrict__ w_v)
{
    __shared__ float ksw[64 * RPAD];
    __shared__ float qsw[8 * RPAD];
    __shared__ float wvs[RPAD];

    int b  = blockIdx.z;
    int kt = blockIdx.y;
    int q0 = blockIdx.x * 8;
    int tid = threadIdx.x;

    const float4* srck = (const float4*)(g_k2 + (b * 8 + kt) * 64 * H_);
    #pragma unroll
    for (int l = 0; l < 8; l++) {
        int i = tid + 256 * l;
        int r = i >> 5, c = i & 31;
        *(float4*)(ksw + r * RPAD + c * 4) = srck[i];
    }
    {
        int r = tid >> 5, c = tid & 31;
        *(float4*)(qsw + r * RPAD + c * 4) =
            ((const float4*)(g_q2 + (b * Q_ + q0 + r) * H_))[c];
    }
    if (tid < 128) {
        __half v = __float2half(w_v[tid]);
        ((__half2*)wvs)[tid] = __halves2half2(v, v);
    }
    __syncthreads();

    int qg = tid >> 6;
    int j  = tid & 63;
    const float4* qa4 = (const float4*)(qsw + (qg * 2    ) * RPAD);
    const float4* qb4 = (const float4*)(qsw + (qg * 2 + 1) * RPAD);
    const float4* kp4 = (const float4*)(ksw + j * RPAD);
    const float4* wv4 = (const float4*)wvs;

    float S00 = 0.f, S01 = 0.f, S10 = 0.f, S11 = 0.f;
    #pragma unroll 4
    for (int hh = 0; hh < 16; hh++) {
        __half2 sa = __float2half2_rn(0.f);
        __half2 sb = __float2half2_rn(0.f);
        #pragma unroll
        for (int t = 0; t < 2; t++) {
            int h4 = hh * 2 + t;
            float4 kv = kp4[h4];
            float4 qa = qa4[h4];
            float4 qb = qb4[h4];
            float4 wf = wv4[h4];
            const __half2* kh  = (const __half2*)&kv;
            const __half2* qah = (const __half2*)&qa;
            const __half2* qbh = (const __half2*)&qb;
            const __half2* wh  = (const __half2*)&wf;
            #pragma unroll
            for (int u = 0; u < 4; u++) {
                __half2 ta = tanh_h2(__hadd2(qah[u], kh[u]));
                __half2 tb = tanh_h2(__hadd2(qbh[u], kh[u]));
                sa = __hfma2(wh[u], ta, sa);
                sb = __hfma2(wh[u], tb, sb);
            }
        }
        float2 fa = __half22float2(sa);
        float2 fb = __half22float2(sb);
        S00 += fa.x; S01 += fa.y;
        S10 += fb.x; S11 += fb.y;
    }

    float* dst = g_sc + (b * Q_ + q0 + qg * 2) * K_ + kt * 128;
    dst[j]           = S00;
    dst[j + 64]      = S01;
    dst[K_ + j]      = S10;
    dst[K_ + j + 64] = S11;
}

// ---------------------------------------------------------------------------
// Kernel 3 v2: masked softmax + attn @ values.
// grid (Q/2, B) = 1024 CTAs, 256 threads, 8KB smem -> ~7 CTAs/SM.
// Softmax: 8 warps = 2 rows x 4 k-segments, smem partial reduce.
// AV: 8 k-slices x 32 float4 columns, aliased smem reduction.
// ---------------------------------------------------------------------------
__global__ __launch_bounds__(256) void smax_av_kernel(
    const float* __restrict__ values, const int* __restrict__ valid_lens,
    float* __restrict__ out)
{
    __shared__ float sc[2 * K_];      // 8KB probs; aliased for AV reduction
    __shared__ float pmax[2][4];
    __shared__ float psum[2][4];

    int b  = blockIdx.y;
    int q0 = blockIdx.x * 2;
    int tid = threadIdx.x;
    int wid = tid >> 5, lane = tid & 31;
    int vlen = valid_lens[b];

    // ---- masked softmax: warp = (row = wid&1, seg = wid>>1 of 256 k) ----
    {
        int row = wid & 1;
        int seg = wid >> 1;
        const float* src = g_sc + (b * Q_ + q0 + row) * K_ + seg * 256;
        float v[8];
        float m = -3e38f;
        #pragma unroll
        for (int jj = 0; jj < 8; jj++) {
            int k = seg * 256 + lane + 32 * jj;
            float s = (k < vlen) ? src[lane + 32 * jj] : -1e6f;
            v[jj] = s;
            m = fmaxf(m, s);
        }
        #pragma unroll
        for (int off = 16; off; off >>= 1)
            m = fmaxf(m, __shfl_xor_sync(0xffffffffu, m, off));
        if (lane == 0) pmax[row][seg] = m;
        __syncthreads();
        float gm = fmaxf(fmaxf(pmax[row][0], pmax[row][1]),
                         fmaxf(pmax[row][2], pmax[row][3]));
        float sum = 0.f;
        #pragma unroll
        for (int jj = 0; jj < 8; jj++) { v[jj] = __expf(v[jj] - gm); sum += v[jj]; }
        #pragma unroll
        for (int off = 16; off; off >>= 1)
            sum += __shfl_xor_sync(0xffffffffu, sum, off);
        if (lane == 0) psum[row][seg] = sum;
        __syncthreads();
        float inv = 1.f / (psum[row][0] + psum[row][1] +
                           psum[row][2] + psum[row][3]);
        float* dstp = sc + row * K_ + seg * 256;
        #pragma unroll
        for (int jj = 0; jj < 8; jj++) dstp[lane + 32 * jj] = v[jj] * inv;
    }
    __syncthreads();

    // ---- attn @ values ----
    int v4 = tid & 31;
    int slice = tid >> 5;
    float4 a0 = make_float4(0.f, 0.f, 0.f, 0.f);
    float4 a1 = make_float4(0.f, 0.f, 0.f, 0.f);
    const float4* vb = (const float4*)(values + b * K_ * DV_);
    #pragma unroll 4
    for (int k = slice; k < K_; k += 8) {
        float4 vv = vb[k * 32 + v4];
        float p0 = sc[k];
        float p1 = sc[K_ + k];
        a0.x += p0 * vv.x; a0.y += p0 * vv.y; a0.z += p0 * vv.z; a0.w += p0 * vv.w;
        a1.x += p1 * vv.x; a1.y += p1 * vv.y; a1.z += p1 * vv.z; a1.w += p1 * vv.w;
    }
    __syncthreads();                  // all sc reads done
    float4* red = (float4*)sc;        // 16 * 32 float4 = 8KB, aliases sc
    red[(slice * 2 + 0) * 32 + v4] = a0;
    red[(slice * 2 + 1) * 32 + v4] = a1;
    __syncthreads();
    if (tid < 64) {
        int r = tid >> 5, c = tid & 31;
        float4 o = make_float4(0.f, 0.f, 0.f, 0.f);
        #pragma unroll
        for (int s = 0; s < 8; s++) {
            float4 t = red[(s * 2 + r) * 32 + c];
            o.x += t.x; o.y += t.y; o.z += t.z; o.w += t.w;
        }
        ((float4*)(out + (b * Q_ + q0 + r) * DV_))[c] = o;
    }
}

extern "C" void kernel_launch(void* const* d_in, const int* in_sizes, int n_in,
                              void* d_out, int out_size)
{
    const float* queries    = (const float*)d_in[0];
    const float* keys       = (const float*)d_in[1];
    const float* values     = (const float*)d_in[2];
    const int*   valid_lens = (const int*)  d_in[3];
    const float* W_q        = (const float*)d_in[4];
    const float* W_k        = (const float*)d_in[5];
    const float* w_v        = (const float*)d_in[6];
    float* out = (float*)d_out;

    proj_kernel<<<(B_ * Q_ + B_ * K_) / 16, 256>>>(queries, keys, W_q, W_k);
    scores_kernel<<<dim3(Q_ / 8, K_ / 128, B_), 256>>>(w_v);
    smax_av_kernel<<<dim3(Q_ / 2, B_), 256>>>(values, valid_lens, out);
}

// round 12
// speedup vs baseline: 1.9699x; 1.2370x over previous
#include <cuda_runtime.h>
#include <cuda_fp16.h>
#include <cuda_bf16.h>

#define B_  8
#define Q_  256
#define K_  1024
#define D_  256
#define H_  128
#define DV_ 128

#define RPAD 132

__device__ __half2 g_q2[B_ * Q_ * H_];
__device__ __half2 g_k2[B_ * 8 * 64 * H_];
__device__ float   g_sc[B_ * Q_ * K_];

__device__ __forceinline__ __half2 tanh_h2(__half2 x) {
    __half2 y;
    asm("tanh.approx.f16x2 %0, %1;"
        : "=r"(*(unsigned int*)&y) : "r"(*(unsigned int*)&x));
    return y;
}

__device__ __forceinline__ unsigned int smem_u32(const void* p) {
    return (unsigned int)__cvta_generic_to_shared(p);
}

__device__ __forceinline__ void ldsm_x4(unsigned int& r0, unsigned int& r1,
                                        unsigned int& r2, unsigned int& r3,
                                        unsigned int a) {
    asm volatile("ldmatrix.sync.aligned.m8n8.x4.shared.b16 {%0,%1,%2,%3}, [%4];"
                 : "=r"(r0), "=r"(r1), "=r"(r2), "=r"(r3) : "r"(a));
}

__device__ __forceinline__ void ldsm_x4t(unsigned int& r0, unsigned int& r1,
                                         unsigned int& r2, unsigned int& r3,
                                         unsigned int a) {
    asm volatile("ldmatrix.sync.aligned.m8n8.x4.trans.shared.b16 {%0,%1,%2,%3}, [%4];"
                 : "=r"(r0), "=r"(r1), "=r"(r2), "=r"(r3) : "r"(a));
}

__device__ __forceinline__ void mma16816(float* c,
                                         unsigned int a0, unsigned int a1,
                                         unsigned int a2, unsigned int a3,
                                         unsigned int b0, unsigned int b1) {
    asm volatile("mma.sync.aligned.m16n8k16.row.col.f32.f16.f16.f32 "
                 "{%0,%1,%2,%3}, {%4,%5,%6,%7}, {%8,%9}, {%0,%1,%2,%3};"
                 : "+f"(c[0]), "+f"(c[1]), "+f"(c[2]), "+f"(c[3])
                 : "r"(a0), "r"(a1), "r"(a2), "r"(a3), "r"(b0), "r"(b1));
}

// ---------------------------------------------------------------------------
// Kernel 1: tensor-core projections. 160 blocks x 256 threads.
// Block = 64 rows x 128 h. A (64x256) + W (256x128) staged fp16 in smem.
// Warp tile m16 x n64; 16 k-steps of ldmatrix + mma.sync (fp32 accum).
// ---------------------------------------------------------------------------
#define SA 264
#define SB 136
#define SC 136
#define SMEM_PROJ ((64 * SA + 256 * SB) * 2)

__global__ __launch_bounds__(256) void proj_mma_kernel(
    const float* __restrict__ queries, const float* __restrict__ keys,
    const float* __restrict__ Wq, const float* __restrict__ Wk)
{
    extern __shared__ __half smh[];
    __half* smA = smh;
    __half* smB = smh + 64 * SA;

    int tid = threadIdx.x;
    int rb = blockIdx.x * 64;
    bool isQ = rb < B_ * Q_;
    const float* src = isQ ? (queries + rb * D_) : (keys + (rb - B_ * Q_) * D_);
    const float* W   = isQ ? Wq : Wk;

    for (int i = tid; i < 4096; i += 256) {
        int r = i >> 6, c4 = i & 63;
        float4 v = ((const float4*)src)[i];
        *(__half2*)&smA[r * SA + c4 * 4]     = __floats2half2_rn(v.x, v.y);
        *(__half2*)&smA[r * SA + c4 * 4 + 2] = __floats2half2_rn(v.z, v.w);
    }
    for (int i = tid; i < 8192; i += 256) {
        int r = i >> 5, c4 = i & 31;
        float4 v = ((const float4*)W)[i];
        *(__half2*)&smB[r * SB + c4 * 4]     = __floats2half2_rn(v.x, v.y);
        *(__half2*)&smB[r * SB + c4 * 4 + 2] = __floats2half2_rn(v.z, v.w);
    }
    __syncthreads();

    int wid = tid >> 5, lane = tid & 31;
    int wm = (wid >> 1) * 16;
    int wn = (wid & 1) * 64;

    float acc[8][4];
    #pragma unroll
    for (int t = 0; t < 8; t++) {
        #pragma unroll
        for (int u = 0; u < 4; u++) acc[t][u] = 0.f;
    }

    unsigned int aBase = smem_u32(smA) +
        ((wm + (lane & 15)) * SA + (lane >> 4) * 8) * 2;
    unsigned int bBase = smem_u32(smB) +
        ((lane & 15) * SB + wn + (lane >> 4) * 8) * 2;

    #pragma unroll
    for (int k = 0; k < 16; k++) {
        unsigned int a0, a1, a2, a3;
        ldsm_x4(a0, a1, a2, a3, aBase + k * 32);
        #pragma unroll
        for (int nt = 0; nt < 4; nt++) {
            unsigned int b0, b1, b2, b3;
            ldsm_x4t(b0, b1, b2, b3, bBase + (k * 16 * SB + nt * 16) * 2);
            mma16816(acc[nt * 2],     a0, a1, a2, a3, b0, b1);
            mma16816(acc[nt * 2 + 1], a0, a1, a2, a3, b2, b3);
        }
    }
    __syncthreads();

    __half* smC = smA;
    #pragma unroll
    for (int t = 0; t < 8; t++) {
        int col = wn + t * 8 + 2 * (lane & 3);
        int r0  = wm + (lane >> 2);
        *(__half2*)&smC[r0 * SC + col]       = __floats2half2_rn(acc[t][0], acc[t][1]);
        *(__half2*)&smC[(r0 + 8) * SC + col] = __floats2half2_rn(acc[t][2], acc[t][3]);
    }
    __syncthreads();

    if (isQ) {
        for (int i = tid; i < 64 * H_; i += 256) {
            int r = i >> 7, h = i & 127;
            __half v = smC[r * SC + h];
            g_q2[(rb + r) * H_ + h] = __halves2half2(v, v);
        }
    } else {
        int rk0 = rb - B_ * Q_;
        int b = rk0 >> 10, kt = (rk0 & 1023) >> 7, slot = (rk0 >> 6) & 1;
        __half* base = (__half*)g_k2 + (b * 8 + kt) * 64 * H_ * 2 + slot;
        for (int i = tid; i < 64 * H_; i += 256) {
            int r = i >> 7, h = i & 127;
            base[(r * H_ + h) * 2] = smC[r * SC + h];
        }
    }
}

// ---------------------------------------------------------------------------
// Kernel 2: scores only (FROZEN). grid (Q/8, K/128, B), 256 threads.
// ---------------------------------------------------------------------------
__global__ __launch_bounds__(256) void scores_kernel(const float* __restrict__ w_v)
{
    __shared__ float ksw[64 * RPAD];
    __shared__ float qsw[8 * RPAD];
    __shared__ float wvs[RPAD];

    int b  = blockIdx.z;
    int kt = blockIdx.y;
    int q0 = blockIdx.x * 8;
    int tid = threadIdx.x;

    const float4* srck = (const float4*)(g_k2 + (b * 8 + kt) * 64 * H_);
    #pragma unroll
    for (int l = 0; l < 8; l++) {
        int i = tid + 256 * l;
        int r = i >> 5, c = i & 31;
        *(float4*)(ksw + r * RPAD + c * 4) = srck[i];
    }
    {
        int r = tid >> 5, c = tid & 31;
        *(float4*)(qsw + r * RPAD + c * 4) =
            ((const float4*)(g_q2 + (b * Q_ + q0 + r) * H_))[c];
    }
    if (tid < 128) {
        __half v = __float2half(w_v[tid]);
        ((__half2*)wvs)[tid] = __halves2half2(v, v);
    }
    __syncthreads();

    int qg = tid >> 6;
    int j  = tid & 63;
    const float4* qa4 = (const float4*)(qsw + (qg * 2    ) * RPAD);
    const float4* qb4 = (const float4*)(qsw + (qg * 2 + 1) * RPAD);
    const float4* kp4 = (const float4*)(ksw + j * RPAD);
    const float4* wv4 = (const float4*)wvs;

    float S00 = 0.f, S01 = 0.f, S10 = 0.f, S11 = 0.f;
    #pragma unroll 4
    for (int hh = 0; hh < 16; hh++) {
        __half2 sa = __float2half2_rn(0.f);
        __half2 sb = __float2half2_rn(0.f);
        #pragma unroll
        for (int t = 0; t < 2; t++) {
            int h4 = hh * 2 + t;
            float4 kv = kp4[h4];
            float4 qa = qa4[h4];
            float4 qb = qb4[h4];
            float4 wf = wv4[h4];
            const __half2* kh  = (const __half2*)&kv;
            const __half2* qah = (const __half2*)&qa;
            const __half2* qbh = (const __half2*)&qb;
            const __half2* wh  = (const __half2*)&wf;
            #pragma unroll
            for (int u = 0; u < 4; u++) {
                __half2 ta = tanh_h2(__hadd2(qah[u], kh[u]));
                __half2 tb = tanh_h2(__hadd2(qbh[u], kh[u]));
                sa = __hfma2(wh[u], ta, sa);
                sb = __hfma2(wh[u], tb, sb);
            }
        }
        float2 fa = __half22float2(sa);
        float2 fb = __half22float2(sb);
        S00 += fa.x; S01 += fa.y;
        S10 += fb.x; S11 += fb.y;
    }

    float* dst = g_sc + (b * Q_ + q0 + qg * 2) * K_ + kt * 128;
    dst[j]           = S00;
    dst[j + 64]      = S01;
    dst[K_ + j]      = S10;
    dst[K_ + j + 64] = S11;
}

// ---------------------------------------------------------------------------
// Kernel 3: masked softmax + attn @ values (round-7 measured-best form).
// grid (Q/8, B) = 256 CTAs, 256 threads, 32KB smem.
// ---------------------------------------------------------------------------
__global__ __launch_bounds__(256) void smax_av_kernel(
    const float* __restrict__ values, const int* __restrict__ valid_lens,
    float* __restrict__ out)
{
    __shared__ float sc[8 * K_];

    int b  = blockIdx.y;
    int q0 = blockIdx.x * 8;
    int tid = threadIdx.x;
    int wid = tid >> 5, lane = tid & 31;
    int vlen = valid_lens[b];

    {
        const float* row = g_sc + (b * Q_ + q0 + wid) * K_;
        float v[32];
        float m = -3e38f;
        #pragma unroll
        for (int jj = 0; jj < 32; jj++) {
            int k = lane + 32 * jj;
            float s = (k < vlen) ? row[k] : -1e6f;
            v[jj] = s;
            m = fmaxf(m, s);
        }
        #pragma unroll
        for (int off = 16; off; off >>= 1)
            m = fmaxf(m, __shfl_xor_sync(0xffffffffu, m, off));
        float sum = 0.f;
        #pragma unroll
        for (int jj = 0; jj < 32; jj++) { v[jj] = __expf(v[jj] - m); sum += v[jj]; }
        #pragma unroll
        for (int off = 16; off; off >>= 1)
            sum += __shfl_xor_sync(0xffffffffu, sum, off);
        float inv = 1.f / sum;
        #pragma unroll
        for (int jj = 0; jj < 32; jj++)
            sc[wid * K_ + lane + 32 * jj] = v[jj] * inv;
    }
    __syncthreads();

    int v4 = tid & 31;
    int slice = tid >> 5;
    float4 acc[8];
    #pragma unroll
    for (int r = 0; r < 8; r++) acc[r] = make_float4(0.f, 0.f, 0.f, 0.f);
    const float4* vb = (const float4*)(values + b * K_ * DV_);
    #pragma unroll 4
    for (int k = slice; k < K_; k += 8) {
        float4 vv = vb[k * 32 + v4];
        #pragma unroll
        for (int r = 0; r < 8; r++) {
            float a = sc[r * K_ + k];
            acc[r].x += a * vv.x; acc[r].y += a * vv.y;
            acc[r].z += a * vv.z; acc[r].w += a * vv.w;
        }
    }
    __syncthreads();
    float4* red = (float4*)sc;
    #pragma unroll
    for (int r = 0; r < 8; r++) red[(slice * 8 + r) * 32 + v4] = acc[r];
    __syncthreads();
    {
        int r = tid >> 5, c = tid & 31;
        float4 o = make_float4(0.f, 0.f, 0.f, 0.f);
        #pragma unroll
        for (int s = 0; s < 8; s++) {
            float4 t = red[(s * 8 + r) * 32 + c];
            o.x += t.x; o.y += t.y; o.z += t.z; o.w += t.w;
        }
        ((float4*)(out + (b * Q_ + q0 + r) * DV_))[c] = o;
    }
}

extern "C" void kernel_launch(void* const* d_in, const int* in_sizes, int n_in,
                              void* d_out, int out_size)
{
    const float* queries    = (const float*)d_in[0];
    const float* keys       = (const float*)d_in[1];
    const float* values     = (const float*)d_in[2];
    const int*   valid_lens = (const int*)  d_in[3];
    const float* W_q        = (const float*)d_in[4];
    const float* W_k        = (const float*)d_in[5];
    const float* w_v        = (const float*)d_in[6];
    float* out = (float*)d_out;

    cudaFuncSetAttribute(proj_mma_kernel,
                         cudaFuncAttributeMaxDynamicSharedMemorySize, SMEM_PROJ);

    proj_mma_kernel<<<(B_ * Q_ + B_ * K_) / 64, 256, SMEM_PROJ>>>(
        queries, keys, W_q, W_k);
    scores_kernel<<<dim3(Q_ / 8, K_ / 128, B_), 256>>>(w_v);
    smax_av_kernel<<<dim3(Q_ / 8, B_), 256>>>(values, valid_lens, out);
}

// round 13
// speedup vs baseline: 1.9706x; 1.0003x over previous
#include <cuda_runtime.h>
#include <cuda_fp16.h>
#include <cuda_bf16.h>

#define B_  8
#define Q_  256
#define K_  1024
#define D_  256
#define H_  128
#define DV_ 128

#define RPAD 132

__device__ __half2 g_q2[B_ * Q_ * H_];
__device__ __half2 g_k2[B_ * 8 * 64 * H_];
__device__ float   g_sc[B_ * Q_ * K_];

__device__ __forceinline__ __half2 tanh_h2(__half2 x) {
    __half2 y;
    asm("tanh.approx.f16x2 %0, %1;"
        : "=r"(*(unsigned int*)&y) : "r"(*(unsigned int*)&x));
    return y;
}

__device__ __forceinline__ unsigned int smem_u32(const void* p) {
    return (unsigned int)__cvta_generic_to_shared(p);
}

__device__ __forceinline__ void ldsm_x4(unsigned int& r0, unsigned int& r1,
                                        unsigned int& r2, unsigned int& r3,
                                        unsigned int a) {
    asm volatile("ldmatrix.sync.aligned.m8n8.x4.shared.b16 {%0,%1,%2,%3}, [%4];"
                 : "=r"(r0), "=r"(r1), "=r"(r2), "=r"(r3) : "r"(a));
}

__device__ __forceinline__ void ldsm_x4t(unsigned int& r0, unsigned int& r1,
                                         unsigned int& r2, unsigned int& r3,
                                         unsigned int a) {
    asm volatile("ldmatrix.sync.aligned.m8n8.x4.trans.shared.b16 {%0,%1,%2,%3}, [%4];"
                 : "=r"(r0), "=r"(r1), "=r"(r2), "=r"(r3) : "r"(a));
}

__device__ __forceinline__ void mma16816(float* c,
                                         unsigned int a0, unsigned int a1,
                                         unsigned int a2, unsigned int a3,
                                         unsigned int b0, unsigned int b1) {
    asm volatile("mma.sync.aligned.m16n8k16.row.col.f32.f16.f16.f32 "
                 "{%0,%1,%2,%3}, {%4,%5,%6,%7}, {%8,%9}, {%0,%1,%2,%3};"
                 : "+f"(c[0]), "+f"(c[1]), "+f"(c[2]), "+f"(c[3])
                 : "r"(a0), "r"(a1), "r"(a2), "r"(a3), "r"(b0), "r"(b1));
}

// ---------------------------------------------------------------------------
// Kernel 1: tensor-core projections. 160 blocks x 512 threads (16 warps).
// Block = 64 rows x 128 h. Warp grid 4m x 4n; warp tile m16 x n32.
// A (64x256) + W (256x128) staged fp16 in smem; fp32 accum.
// ---------------------------------------------------------------------------
#define SA 264
#define SB 136
#define SC 136
#define SMEM_PROJ ((64 * SA + 256 * SB) * 2)

__global__ __launch_bounds__(512) void proj_mma_kernel(
    const float* __restrict__ queries, const float* __restrict__ keys,
    const float* __restrict__ Wq, const float* __restrict__ Wk)
{
    extern __shared__ __half smh[];
    __half* smA = smh;
    __half* smB = smh + 64 * SA;

    int tid = threadIdx.x;
    int rb = blockIdx.x * 64;
    bool isQ = rb < B_ * Q_;
    const float* src = isQ ? (queries + rb * D_) : (keys + (rb - B_ * Q_) * D_);
    const float* W   = isQ ? Wq : Wk;

    // stage A: 64 x 256 fp32 -> fp16 (4096 float4, 8 per thread)
    for (int i = tid; i < 4096; i += 512) {
        int r = i >> 6, c4 = i & 63;
        float4 v = ((const float4*)src)[i];
        *(__half2*)&smA[r * SA + c4 * 4]     = __floats2half2_rn(v.x, v.y);
        *(__half2*)&smA[r * SA + c4 * 4 + 2] = __floats2half2_rn(v.z, v.w);
    }
    // stage W: 256 x 128 fp32 -> fp16 (8192 float4, 16 per thread)
    for (int i = tid; i < 8192; i += 512) {
        int r = i >> 5, c4 = i & 31;
        float4 v = ((const float4*)W)[i];
        *(__half2*)&smB[r * SB + c4 * 4]     = __floats2half2_rn(v.x, v.y);
        *(__half2*)&smB[r * SB + c4 * 4 + 2] = __floats2half2_rn(v.z, v.w);
    }
    __syncthreads();

    int wid = tid >> 5, lane = tid & 31;
    int wm = (wid >> 2) * 16;          // 4 m-tiles
    int wn = (wid & 3) * 32;           // 4 n-tiles

    float acc[4][4];
    #pragma unroll
    for (int t = 0; t < 4; t++) {
        #pragma unroll
        for (int u = 0; u < 4; u++) acc[t][u] = 0.f;
    }

    unsigned int aBase = smem_u32(smA) +
        ((wm + (lane & 15)) * SA + (lane >> 4) * 8) * 2;
    unsigned int bBase = smem_u32(smB) +
        ((lane & 15) * SB + wn + (lane >> 4) * 8) * 2;

    #pragma unroll
    for (int k = 0; k < 16; k++) {
        unsigned int a0, a1, a2, a3;
        ldsm_x4(a0, a1, a2, a3, aBase + k * 32);
        #pragma unroll
        for (int nt = 0; nt < 2; nt++) {
            unsigned int b0, b1, b2, b3;
            ldsm_x4t(b0, b1, b2, b3, bBase + (k * 16 * SB + nt * 16) * 2);
            mma16816(acc[nt * 2],     a0, a1, a2, a3, b0, b1);
            mma16816(acc[nt * 2 + 1], a0, a1, a2, a3, b2, b3);
        }
    }
    __syncthreads();

    // stage C (fp16) into smem (reuse A region), then coalesced writeout
    __half* smC = smA;
    #pragma unroll
    for (int t = 0; t < 4; t++) {
        int col = wn + t * 8 + 2 * (lane & 3);
        int r0  = wm + (lane >> 2);
        *(__half2*)&smC[r0 * SC + col]       = __floats2half2_rn(acc[t][0], acc[t][1]);
        *(__half2*)&smC[(r0 + 8) * SC + col] = __floats2half2_rn(acc[t][2], acc[t][3]);
    }
    __syncthreads();

    if (isQ) {
        for (int i = tid; i < 64 * H_; i += 512) {
            int r = i >> 7, h = i & 127;
            __half v = smC[r * SC + h];
            g_q2[(rb + r) * H_ + h] = __halves2half2(v, v);
        }
    } else {
        int rk0 = rb - B_ * Q_;
        int b = rk0 >> 10, kt = (rk0 & 1023) >> 7, slot = (rk0 >> 6) & 1;
        __half* base = (__half*)g_k2 + (b * 8 + kt) * 64 * H_ * 2 + slot;
        for (int i = tid; i < 64 * H_; i += 512) {
            int r = i >> 7, h = i & 127;
            base[(r * H_ + h) * 2] = smC[r * SC + h];
        }
    }
}

// ---------------------------------------------------------------------------
// Kernel 2: scores only (FROZEN). grid (Q/8, K/128, B), 256 threads.
// ---------------------------------------------------------------------------
__global__ __launch_bounds__(256) void scores_kernel(const float* __restrict__ w_v)
{
    __shared__ float ksw[64 * RPAD];
    __shared__ float qsw[8 * RPAD];
    __shared__ float wvs[RPAD];

    int b  = blockIdx.z;
    int kt = blockIdx.y;
    int q0 = blockIdx.x * 8;
    int tid = threadIdx.x;

    const float4* srck = (const float4*)(g_k2 + (b * 8 + kt) * 64 * H_);
    #pragma unroll
    for (int l = 0; l < 8; l++) {
        int i = tid + 256 * l;
        int r = i >> 5, c = i & 31;
        *(float4*)(ksw + r * RPAD + c * 4) = srck[i];
    }
    {
        int r = tid >> 5, c = tid & 31;
        *(float4*)(qsw + r * RPAD + c * 4) =
            ((const float4*)(g_q2 + (b * Q_ + q0 + r) * H_))[c];
    }
    if (tid < 128) {
        __half v = __float2half(w_v[tid]);
        ((__half2*)wvs)[tid] = __halves2half2(v, v);
    }
    __syncthreads();

    int qg = tid >> 6;
    int j  = tid & 63;
    const float4* qa4 = (const float4*)(qsw + (qg * 2    ) * RPAD);
    const float4* qb4 = (const float4*)(qsw + (qg * 2 + 1) * RPAD);
    const float4* kp4 = (const float4*)(ksw + j * RPAD);
    const float4* wv4 = (const float4*)wvs;

    float S00 = 0.f, S01 = 0.f, S10 = 0.f, S11 = 0.f;
    #pragma unroll 4
    for (int hh = 0; hh < 16; hh++) {
        __half2 sa = __float2half2_rn(0.f);
        __half2 sb = __float2half2_rn(0.f);
        #pragma unroll
        for (int t = 0; t < 2; t++) {
            int h4 = hh * 2 + t;
            float4 kv = kp4[h4];
            float4 qa = qa4[h4];
            float4 qb = qb4[h4];
            float4 wf = wv4[h4];
            const __half2* kh  = (const __half2*)&kv;
            const __half2* qah = (const __half2*)&qa;
            const __half2* qbh = (const __half2*)&qb;
            const __half2* wh  = (const __half2*)&wf;
            #pragma unroll
            for (int u = 0; u < 4; u++) {
                __half2 ta = tanh_h2(__hadd2(qah[u], kh[u]));
                __half2 tb = tanh_h2(__hadd2(qbh[u], kh[u]));
                sa = __hfma2(wh[u], ta, sa);
                sb = __hfma2(wh[u], tb, sb);
            }
        }
        float2 fa = __half22float2(sa);
        float2 fb = __half22float2(sb);
        S00 += fa.x; S01 += fa.y;
        S10 += fb.x; S11 += fb.y;
    }

    float* dst = g_sc + (b * Q_ + q0 + qg * 2) * K_ + kt * 128;
    dst[j]           = S00;
    dst[j + 64]      = S01;
    dst[K_ + j]      = S10;
    dst[K_ + j + 64] = S11;
}

// ---------------------------------------------------------------------------
// Kernel 3: masked softmax + attn @ values (FROZEN). grid (Q/8, B).
// ---------------------------------------------------------------------------
__global__ __launch_bounds__(256) void smax_av_kernel(
    const float* __restrict__ values, const int* __restrict__ valid_lens,
    float* __restrict__ out)
{
    __shared__ float sc[8 * K_];

    int b  = blockIdx.y;
    int q0 = blockIdx.x * 8;
    int tid = threadIdx.x;
    int wid = tid >> 5, lane = tid & 31;
    int vlen = valid_lens[b];

    {
        const float* row = g_sc + (b * Q_ + q0 + wid) * K_;
        float v[32];
        float m = -3e38f;
        #pragma unroll
        for (int jj = 0; jj < 32; jj++) {
            int k = lane + 32 * jj;
            float s = (k < vlen) ? row[k] : -1e6f;
            v[jj] = s;
            m = fmaxf(m, s);
        }
        #pragma unroll
        for (int off = 16; off; off >>= 1)
            m = fmaxf(m, __shfl_xor_sync(0xffffffffu, m, off));
        float sum = 0.f;
        #pragma unroll
        for (int jj = 0; jj < 32; jj++) { v[jj] = __expf(v[jj] - m); sum += v[jj]; }
        #pragma unroll
        for (int off = 16; off; off >>= 1)
            sum += __shfl_xor_sync(0xffffffffu, sum, off);
        float inv = 1.f / sum;
        #pragma unroll
        for (int jj = 0; jj < 32; jj++)
            sc[wid * K_ + lane + 32 * jj] = v[jj] * inv;
    }
    __syncthreads();

    int v4 = tid & 31;
    int slice = tid >> 5;
    float4 acc[8];
    #pragma unroll
    for (int r = 0; r < 8; r++) acc[r] = make_float4(0.f, 0.f, 0.f, 0.f);
    const float4* vb = (const float4*)(values + b * K_ * DV_);
    #pragma unroll 4
    for (int k = slice; k < K_; k += 8) {
        float4 vv = vb[k * 32 + v4];
        #pragma unroll
        for (int r = 0; r < 8; r++) {
            float a = sc[r * K_ + k];
            acc[r].x += a * vv.x; acc[r].y += a * vv.y;
            acc[r].z += a * vv.z; acc[r].w += a * vv.w;
        }
    }
    __syncthreads();
    float4* red = (float4*)sc;
    #pragma unroll
    for (int r = 0; r < 8; r++) red[(slice * 8 + r) * 32 + v4] = acc[r];
    __syncthreads();
    {
        int r = tid >> 5, c = tid & 31;
        float4 o = make_float4(0.f, 0.f, 0.f, 0.f);
        #pragma unroll
        for (int s = 0; s < 8; s++) {
            float4 t = red[(s * 8 + r) * 32 + c];
            o.x += t.x; o.y += t.y; o.z += t.z; o.w += t.w;
        }
        ((float4*)(out + (b * Q_ + q0 + r) * DV_))[c] = o;
    }
}

extern "C" void kernel_launch(void* const* d_in, const int* in_sizes, int n_in,
                              void* d_out, int out_size)
{
    const float* queries    = (const float*)d_in[0];
    const float* keys       = (const float*)d_in[1];
    const float* values     = (const float*)d_in[2];
    const int*   valid_lens = (const int*)  d_in[3];
    const float* W_q        = (const float*)d_in[4];
    const float* W_k        = (const float*)d_in[5];
    const float* w_v        = (const float*)d_in[6];
    float* out = (float*)d_out;

    cudaFuncSetAttribute(proj_mma_kernel,
                         cudaFuncAttributeMaxDynamicSharedMemorySize, SMEM_PROJ);

    proj_mma_kernel<<<(B_ * Q_ + B_ * K_) / 64, 512, SMEM_PROJ>>>(
        queries, keys, W_q, W_k);
    scores_kernel<<<dim3(Q_ / 8, K_ / 128, B_), 256>>>(w_v);
    smax_av_kernel<<<dim3(Q_ / 8, B_), 256>>>(values, valid_lens, out);
}

// round 15
// speedup vs baseline: 2.0159x; 1.0230x over previous
#include <cuda_runtime.h>
#include <cuda_fp16.h>
#include <cuda_bf16.h>

#define B_  8
#define Q_  256
#define K_  1024
#define D_  256
#define H_  128
#define DV_ 128

#define RPAD 132

__device__ __half2 g_q2[B_ * Q_ * H_];
__device__ __half2 g_k2[B_ * 8 * 64 * H_];
__device__ float   g_sc[B_ * Q_ * K_];

__device__ __forceinline__ __half2 tanh_h2(__half2 x) {
    __half2 y;
    asm("tanh.approx.f16x2 %0, %1;"
        : "=r"(*(unsigned int*)&y) : "r"(*(unsigned int*)&x));
    return y;
}

__device__ __forceinline__ unsigned int smem_u32(const void* p) {
    return (unsigned int)__cvta_generic_to_shared(p);
}

__device__ __forceinline__ void ldsm_x4(unsigned int& r0, unsigned int& r1,
                                        unsigned int& r2, unsigned int& r3,
                                        unsigned int a) {
    asm volatile("ldmatrix.sync.aligned.m8n8.x4.shared.b16 {%0,%1,%2,%3}, [%4];"
                 : "=r"(r0), "=r"(r1), "=r"(r2), "=r"(r3) : "r"(a));
}

__device__ __forceinline__ void ldsm_x4t(unsigned int& r0, unsigned int& r1,
                                         unsigned int& r2, unsigned int& r3,
                                         unsigned int a) {
    asm volatile("ldmatrix.sync.aligned.m8n8.x4.trans.shared.b16 {%0,%1,%2,%3}, [%4];"
                 : "=r"(r0), "=r"(r1), "=r"(r2), "=r"(r3) : "r"(a));
}

__device__ __forceinline__ void mma16816(float* c,
                                         unsigned int a0, unsigned int a1,
                                         unsigned int a2, unsigned int a3,
                                         unsigned int b0, unsigned int b1) {
    asm volatile("mma.sync.aligned.m16n8k16.row.col.f32.f16.f16.f32 "
                 "{%0,%1,%2,%3}, {%4,%5,%6,%7}, {%8,%9}, {%0,%1,%2,%3};"
                 : "+f"(c[0]), "+f"(c[1]), "+f"(c[2]), "+f"(c[3])
                 : "r"(a0), "r"(a1), "r"(a2), "r"(a3), "r"(b0), "r"(b1));
}

// ---------------------------------------------------------------------------
// Kernel 1: tensor-core projections. 160 blocks x 512 threads (16 warps).
// Block = 64 rows x 128 h. Warp grid 4m x 4n; warp tile m16 x n32.
// Staging uses explicit register batching (8 float4 in flight) to raise MLP.
// ---------------------------------------------------------------------------
#define SA 264
#define SB 136
#define SC 136
#define SMEM_PROJ ((64 * SA + 256 * SB) * 2)

__global__ __launch_bounds__(512) void proj_mma_kernel(
    const float* __restrict__ queries, const float* __restrict__ keys,
    const float* __restrict__ Wq, const float* __restrict__ Wk)
{
    extern __shared__ __half smh[];
    __half* smA = smh;
    __half* smB = smh + 64 * SA;

    int tid = threadIdx.x;
    int rb = blockIdx.x * 64;
    bool isQ = rb < B_ * Q_;
    const float* src = isQ ? (queries + rb * D_) : (keys + (rb - B_ * Q_) * D_);
    const float* W   = isQ ? Wq : Wk;

    // ---- stage A: 4096 float4 (8/thread), batched loads then stores ----
    {
        float4 v[8];
        #pragma unroll
        for (int l = 0; l < 8; l++) v[l] = ((const float4*)src)[tid + 512 * l];
        #pragma unroll
        for (int l = 0; l < 8; l++) {
            int i = tid + 512 * l;
            int r = i >> 6, c4 = i & 63;
            *(__half2*)&smA[r * SA + c4 * 4]     = __floats2half2_rn(v[l].x, v[l].y);
            *(__half2*)&smA[r * SA + c4 * 4 + 2] = __floats2half2_rn(v[l].z, v[l].w);
        }
    }
    // ---- stage W: 8192 float4 (16/thread), two batches of 8 ----
    #pragma unroll
    for (int g = 0; g < 2; g++) {
        float4 v[8];
        #pragma unroll
        for (int l = 0; l < 8; l++)
            v[l] = ((const float4*)W)[tid + 512 * (g * 8 + l)];
        #pragma unroll
        for (int l = 0; l < 8; l++) {
            int i = tid + 512 * (g * 8 + l);
            int r = i >> 5, c4 = i & 31;
            *(__half2*)&smB[r * SB + c4 * 4]     = __floats2half2_rn(v[l].x, v[l].y);
            *(__half2*)&smB[r * SB + c4 * 4 + 2] = __floats2half2_rn(v[l].z, v[l].w);
        }
    }
    __syncthreads();

    int wid = tid >> 5, lane = tid & 31;
    int wm = (wid >> 2) * 16;          // 4 m-tiles
    int wn = (wid & 3) * 32;           // 4 n-tiles

    float acc[4][4];
    #pragma unroll
    for (int t = 0; t < 4; t++) {
        #pragma unroll
        for (int u = 0; u < 4; u++) acc[t][u] = 0.f;
    }

    unsigned int aBase = smem_u32(smA) +
        ((wm + (lane & 15)) * SA + (lane >> 4) * 8) * 2;
    unsigned int bBase = smem_u32(smB) +
        ((lane & 15) * SB + wn + (lane >> 4) * 8) * 2;

    #pragma unroll
    for (int k = 0; k < 16; k++) {
        unsigned int a0, a1, a2, a3;
        ldsm_x4(a0, a1, a2, a3, aBase + k * 32);
        #pragma unroll
        for (int nt = 0; nt < 2; nt++) {
            unsigned int b0, b1, b2, b3;
            ldsm_x4t(b0, b1, b2, b3, bBase + (k * 16 * SB + nt * 16) * 2);
            mma16816(acc[nt * 2],     a0, a1, a2, a3, b0, b1);
            mma16816(acc[nt * 2 + 1], a0, a1, a2, a3, b2, b3);
        }
    }
    __syncthreads();

    __half* smC = smA;
    #pragma unroll
    for (int t = 0; t < 4; t++) {
        int col = wn + t * 8 + 2 * (lane & 3);
        int r0  = wm + (lane >> 2);
        *(__half2*)&smC[r0 * SC + col]       = __floats2half2_rn(acc[t][0], acc[t][1]);
        *(__half2*)&smC[(r0 + 8) * SC + col] = __floats2half2_rn(acc[t][2], acc[t][3]);
    }
    __syncthreads();

    if (isQ) {
        #pragma unroll
        for (int l = 0; l < 16; l++) {
            int i = tid + 512 * l;
            int r = i >> 7, h = i & 127;
            __half v = smC[r * SC + h];
            g_q2[(rb + r) * H_ + h] = __halves2half2(v, v);
        }
    } else {
        int rk0 = rb - B_ * Q_;
        int b = rk0 >> 10, kt = (rk0 & 1023) >> 7, slot = (rk0 >> 6) & 1;
        __half* base = (__half*)g_k2 + (b * 8 + kt) * 64 * H_ * 2 + slot;
        #pragma unroll
        for (int l = 0; l < 16; l++) {
            int i = tid + 512 * l;
            int r = i >> 7, h = i & 127;
            base[(r * H_ + h) * 2] = smC[r * SC + h];
        }
    }
}

// ---------------------------------------------------------------------------
// Kernel 2: scores only (FROZEN). grid (Q/8, K/128, B), 256 threads.
// ---------------------------------------------------------------------------
__global__ __launch_bounds__(256) void scores_kernel(const float* __restrict__ w_v)
{
    __shared__ float ksw[64 * RPAD];
    __shared__ float qsw[8 * RPAD];
    __shared__ float wvs[RPAD];

    int b  = blockIdx.z;
    int kt = blockIdx.y;
    int q0 = blockIdx.x * 8;
    int tid = threadIdx.x;

    const float4* srck = (const float4*)(g_k2 + (b * 8 + kt) * 64 * H_);
    #pragma unroll
    for (int l = 0; l < 8; l++) {
        int i = tid + 256 * l;
        int r = i >> 5, c = i & 31;
        *(float4*)(ksw + r * RPAD + c * 4) = srck[i];
    }
    {
        int r = tid >> 5, c = tid & 31;
        *(float4*)(qsw + r * RPAD + c * 4) =
            ((const float4*)(g_q2 + (b * Q_ + q0 + r) * H_))[c];
    }
    if (tid < 128) {
        __half v = __float2half(w_v[tid]);
        ((__half2*)wvs)[tid] = __halves2half2(v, v);
    }
    __syncthreads();

    int qg = tid >> 6;
    int j  = tid & 63;
    const float4* qa4 = (const float4*)(qsw + (qg * 2    ) * RPAD);
    const float4* qb4 = (const float4*)(qsw + (qg * 2 + 1) * RPAD);
    const float4* kp4 = (const float4*)(ksw + j * RPAD);
    const float4* wv4 = (const float4*)wvs;

    float S00 = 0.f, S01 = 0.f, S10 = 0.f, S11 = 0.f;
    #pragma unroll 4
    for (int hh = 0; hh < 16; hh++) {
        __half2 sa = __float2half2_rn(0.f);
        __half2 sb = __float2half2_rn(0.f);
        #pragma unroll
        for (int t = 0; t < 2; t++) {
            int h4 = hh * 2 + t;
            float4 kv = kp4[h4];
            float4 qa = qa4[h4];
            float4 qb = qb4[h4];
            float4 wf = wv4[h4];
            const __half2* kh  = (const __half2*)&kv;
            const __half2* qah = (const __half2*)&qa;
            const __half2* qbh = (const __half2*)&qb;
            const __half2* wh  = (const __half2*)&wf;
            #pragma unroll
            for (int u = 0; u < 4; u++) {
                __half2 ta = tanh_h2(__hadd2(qah[u], kh[u]));
                __half2 tb = tanh_h2(__hadd2(qbh[u], kh[u]));
                sa = __hfma2(wh[u], ta, sa);
                sb = __hfma2(wh[u], tb, sb);
            }
        }
        float2 fa = __half22float2(sa);
        float2 fb = __half22float2(sb);
        S00 += fa.x; S01 += fa.y;
        S10 += fb.x; S11 += fb.y;
    }

    float* dst = g_sc + (b * Q_ + q0 + qg * 2) * K_ + kt * 128;
    dst[j]           = S00;
    dst[j + 64]      = S01;
    dst[K_ + j]      = S10;
    dst[K_ + j + 64] = S11;
}

// ---------------------------------------------------------------------------
// Kernel 3: masked softmax + attn @ values (FROZEN). grid (Q/8, B).
// ---------------------------------------------------------------------------
__global__ __launch_bounds__(256) void smax_av_kernel(
    const float* __restrict__ values, const int* __restrict__ valid_lens,
    float* __restrict__ out)
{
    __shared__ float sc[8 * K_];

    int b  = blockIdx.y;
    int q0 = blockIdx.x * 8;
    int tid = threadIdx.x;
    int wid = tid >> 5, lane = tid & 31;
    int vlen = valid_lens[b];

    {
        const float* row = g_sc + (b * Q_ + q0 + wid) * K_;
        float v[32];
        float m = -3e38f;
        #pragma unroll
        for (int jj = 0; jj < 32; jj++) {
            int k = lane + 32 * jj;
            float s = (k < vlen) ? row[k] : -1e6f;
            v[jj] = s;
            m = fmaxf(m, s);
        }
        #pragma unroll
        for (int off = 16; off; off >>= 1)
            m = fmaxf(m, __shfl_xor_sync(0xffffffffu, m, off));
        float sum = 0.f;
        #pragma unroll
        for (int jj = 0; jj < 32; jj++) { v[jj] = __expf(v[jj] - m); sum += v[jj]; }
        #pragma unroll
        for (int off = 16; off; off >>= 1)
            sum += __shfl_xor_sync(0xffffffffu, sum, off);
        float inv = 1.f / sum;
        #pragma unroll
        for (int jj = 0; jj < 32; jj++)
            sc[wid * K_ + lane + 32 * jj] = v[jj] * inv;
    }
    __syncthreads();

    int v4 = tid & 31;
    int slice = tid >> 5;
    float4 acc[8];
    #pragma unroll
    for (int r = 0; r < 8; r++) acc[r] = make_float4(0.f, 0.f, 0.f, 0.f);
    const float4* vb = (const float4*)(values + b * K_ * DV_);
    #pragma unroll 4
    for (int k = slice; k < K_; k += 8) {
        float4 vv = vb[k * 32 + v4];
        #pragma unroll
        for (int r = 0; r < 8; r++) {
            float a = sc[r * K_ + k];
            acc[r].x += a * vv.x; acc[r].y += a * vv.y;
            acc[r].z += a * vv.z; acc[r].w += a * vv.w;
        }
    }
    __syncthreads();
    float4* red = (float4*)sc;
    #pragma unroll
    for (int r = 0; r < 8; r++) red[(slice * 8 + r) * 32 + v4] = acc[r];
    __syncthreads();
    {
        int r = tid >> 5, c = tid & 31;
        float4 o = make_float4(0.f, 0.f, 0.f, 0.f);
        #pragma unroll
        for (int s = 0; s < 8; s++) {
            float4 t = red[(s * 8 + r) * 32 + c];
            o.x += t.x; o.y += t.y; o.z += t.z; o.w += t.w;
        }
        ((float4*)(out + (b * Q_ + q0 + r) * DV_))[c] = o;
    }
}

extern "C" void kernel_launch(void* const* d_in, const int* in_sizes, int n_in,
                              void* d_out, int out_size)
{
    const float* queries    = (const float*)d_in[0];
    const float* keys       = (const float*)d_in[1];
    const float* values     = (const float*)d_in[2];
    const int*   valid_lens = (const int*)  d_in[3];
    const float* W_q        = (const float*)d_in[4];
    const float* W_k        = (const float*)d_in[5];
    const float* w_v        = (const float*)d_in[6];
    float* out = (float*)d_out;

    cudaFuncSetAttribute(proj_mma_kernel,
                         cudaFuncAttributeMaxDynamicSharedMemorySize, SMEM_PROJ);

    proj_mma_kernel<<<(B_ * Q_ + B_ * K_) / 64, 512, SMEM_PROJ>>>(
        queries, keys, W_q, W_k);
    scores_kernel<<<dim3(Q_ / 8, K_ / 128, B_), 256>>>(w_v);
    smax_av_kernel<<<dim3(Q_ / 8, B_), 256>>>(values, valid_lens, out);
}